// round 6
// baseline (speedup 1.0000x reference)
#include <cuda_runtime.h>
#include <cuda_bf16.h>
#include <stdint.h>
#include <math.h>

// Problem constants
#define BATCH 2
#define SEQ   2048
#define DIM   1024
#define HEADS 16
#define HD    64
#define MTOK  (BATCH * SEQ)            // 4096 tokens
#define HALF  (DIM / 2)                // 512

// GEMM tiling: CTA tile 128x256, warp tile 64x64, K-chunk 32, 3 stages
#define GM 128
#define GN 256
#define GKC 32                          // bf16 k-elems per chunk (64 bytes/row)
#define NCHUNK (DIM / GKC)              // 32
#define NSTAGE 3
#define RA_HI 0
#define RA_LO 8192
#define RB_HI 16384
#define RB_LO 32768
#define STAGE_BYTES 49152
#define SMEM_TOTAL (NSTAGE * STAGE_BYTES)   // 144 KB

// ---------------------------------------------------------------------------
// Device scratch (no cudaMalloc allowed)
// ---------------------------------------------------------------------------
__device__ float g_q[MTOK * DIM];
__device__ float g_k[MTOK * DIM];
__device__ float g_v[MTOK * DIM];
__device__ float g_cos[SEQ * HALF];
__device__ float g_sin[SEQ * HALF];
__device__ float g_invf[HALF];

__device__ __nv_bfloat16 g_in_hi[MTOK * DIM], g_in_lo[MTOK * DIM];
__device__ __nv_bfloat16 g_cx_hi[MTOK * DIM], g_cx_lo[MTOK * DIM];
__device__ __nv_bfloat16 g_xx_hi[MTOK * DIM], g_xx_lo[MTOK * DIM];
__device__ __nv_bfloat16 g_wq_hi[DIM * DIM], g_wq_lo[DIM * DIM];
__device__ __nv_bfloat16 g_wk_hi[DIM * DIM], g_wk_lo[DIM * DIM];
__device__ __nv_bfloat16 g_wv_hi[DIM * DIM], g_wv_lo[DIM * DIM];
__device__ __nv_bfloat16 g_wo_hi[DIM * DIM], g_wo_lo[DIM * DIM];

// ---------------------------------------------------------------------------
// Helpers
// ---------------------------------------------------------------------------
__device__ __forceinline__ uint32_t smem_u32(const void* p) {
    uint32_t a;
    asm("{ .reg .u64 t; cvta.to.shared.u64 t, %1; cvt.u32.u64 %0, t; }"
        : "=r"(a) : "l"(p));
    return a;
}

__device__ __forceinline__ void cp16(uint32_t smem, const void* g) {
    asm volatile("cp.async.cg.shared.global [%0], [%1], 16;" :: "r"(smem), "l"(g));
}
__device__ __forceinline__ void cp_commit() {
    asm volatile("cp.async.commit_group;" ::: "memory");
}
template <int N>
__device__ __forceinline__ void cp_wait() {
    asm volatile("cp.async.wait_group %0;" :: "n"(N) : "memory");
}

// 64B-row swizzle (Swizzle<2,4,3> equivalent): XOR 16B-col bits [5:4] with row bits [2:1]
#define SWZ64(off) ((uint32_t)(off) ^ ((((uint32_t)(off)) >> 3) & 0x30u))

__device__ __forceinline__ void ldsm_x4(uint32_t* r, uint32_t addr) {
    asm volatile("ldmatrix.sync.aligned.m8n8.x4.shared.b16 {%0,%1,%2,%3}, [%4];"
                 : "=r"(r[0]), "=r"(r[1]), "=r"(r[2]), "=r"(r[3]) : "r"(addr));
}

__device__ __forceinline__ void mma16816(float* d, const uint32_t* a,
                                         uint32_t b0, uint32_t b1) {
    asm volatile(
        "mma.sync.aligned.m16n8k16.row.col.f32.bf16.bf16.f32 "
        "{%0,%1,%2,%3}, {%4,%5,%6,%7}, {%8,%9}, {%0,%1,%2,%3};"
        : "+f"(d[0]), "+f"(d[1]), "+f"(d[2]), "+f"(d[3])
        : "r"(a[0]), "r"(a[1]), "r"(a[2]), "r"(a[3]), "r"(b0), "r"(b1));
}

// ---------------------------------------------------------------------------
// RoPE tables
// ---------------------------------------------------------------------------
__global__ void rope_inv_kernel() {
    int j = threadIdx.x;
    if (j < HALF) {
        double inv = exp(-((double)(2 * j) / (double)DIM) * log(10000.0));
        g_invf[j] = (float)inv;
    }
}

__global__ void rope_tab_kernel() {
    int idx = blockIdx.x * 256 + threadIdx.x;
    int s = idx >> 9;
    int j = idx & (HALF - 1);
    float arg = (float)s * g_invf[j];
    float sn, cs;
    sincosf(arg, &sn, &cs);
    g_cos[idx] = cs;
    g_sin[idx] = sn;
}

// ---------------------------------------------------------------------------
// fp32 -> bf16 hi/lo split (elementwise, same layout)
// ---------------------------------------------------------------------------
__global__ void convert_act_kernel(const float* __restrict__ X,
                                   __nv_bfloat16* __restrict__ hi,
                                   __nv_bfloat16* __restrict__ lo) {
    int i = (blockIdx.x * 256 + threadIdx.x) * 4;
    float4 x = *(const float4*)(X + i);
    __nv_bfloat16 h0 = __float2bfloat16(x.x);
    __nv_bfloat16 h1 = __float2bfloat16(x.y);
    __nv_bfloat16 h2 = __float2bfloat16(x.z);
    __nv_bfloat16 h3 = __float2bfloat16(x.w);
    *(__nv_bfloat162*)(hi + i)     = __halves2bfloat162(h0, h1);
    *(__nv_bfloat162*)(hi + i + 2) = __halves2bfloat162(h2, h3);
    __nv_bfloat16 l0 = __float2bfloat16(x.x - __bfloat162float(h0));
    __nv_bfloat16 l1 = __float2bfloat16(x.y - __bfloat162float(h1));
    __nv_bfloat16 l2 = __float2bfloat16(x.z - __bfloat162float(h2));
    __nv_bfloat16 l3 = __float2bfloat16(x.w - __bfloat162float(h3));
    *(__nv_bfloat162*)(lo + i)     = __halves2bfloat162(l0, l1);
    *(__nv_bfloat162*)(lo + i + 2) = __halves2bfloat162(l2, l3);
}

// ---------------------------------------------------------------------------
// W [K][N] fp32 -> transposed hi/lo bf16 [N][K]
// ---------------------------------------------------------------------------
__global__ void convert_w_kernel(const float* __restrict__ W,
                                 __nv_bfloat16* __restrict__ hi,
                                 __nv_bfloat16* __restrict__ lo) {
    __shared__ float t[32][33];
    int k0 = blockIdx.y * 32, n0 = blockIdx.x * 32;
    int tx = threadIdx.x, ty = threadIdx.y;   // 32 x 8
#pragma unroll
    for (int i = 0; i < 32; i += 8)
        t[ty + i][tx] = W[(size_t)(k0 + ty + i) * DIM + n0 + tx];
    __syncthreads();
#pragma unroll
    for (int i = 0; i < 32; i += 8) {
        float x = t[tx][ty + i];              // W[k0+tx][n0+ty+i]
        __nv_bfloat16 h = __float2bfloat16(x);
        float r = x - __bfloat162float(h);
        size_t o = (size_t)(n0 + ty + i) * DIM + k0 + tx;
        hi[o] = h;
        lo[o] = __float2bfloat16(r);
    }
}

// ---------------------------------------------------------------------------
// bf16x3 mma.sync GEMM:  C = Ahi@B^T(hi) + Ahi@B^T(lo) + Alo@B^T(hi) + bias
// A: [m][k] K-major bf16 hi/lo.  B: [n][k] K-major bf16 hi/lo (pre-transposed W).
// CTA tile 128x256, 8 warps (2M x 4N), warp tile 64x64 -> LDSM:MMA = 1:6.
// ---------------------------------------------------------------------------
__global__ void __launch_bounds__(256, 1)
gemm_mma(const __nv_bfloat16* __restrict__ Ahi, const __nv_bfloat16* __restrict__ Alo,
         const __nv_bfloat16* __restrict__ Bhi, const __nv_bfloat16* __restrict__ Blo,
         const float* __restrict__ bias, float* __restrict__ C) {
    extern __shared__ __align__(1024) char smem[];
    const int tid  = threadIdx.x;
    const int wid  = tid >> 5;
    const int lane = tid & 31;
    const int row0 = blockIdx.y * GM;
    const int col0 = blockIdx.x * GN;
    const uint32_t sb = smem_u32(smem);

    const int wm = wid >> 2;           // 0..1
    const int wn = wid & 3;            // 0..3
    const int m_base = wm * 64;
    const int n_base = wn * 64;

    // ldmatrix lane address components (64B rows)
    const int a_row_in = lane & 15;
    const int a_kseg   = (lane >> 4) * 16;
    const int b_row_in = (lane & 7) + ((lane >> 4) & 1) * 8;
    const int b_kseg   = ((lane >> 3) & 1) * 16;

    float acc[4][8][4];
#pragma unroll
    for (int i = 0; i < 4; i++)
#pragma unroll
        for (int j = 0; j < 8; j++)
#pragma unroll
            for (int e = 0; e < 4; e++) acc[i][j][e] = 0.0f;

    // --- chunk loader: 32 k-elems (64B/row), A 128 rows, B 256 rows, hi+lo ---
    auto issue = [&](int c) {
        const uint32_t st = sb + (uint32_t)(c % NSTAGE) * STAGE_BYTES;
        const int k0 = c * GKC;
        // A: 512 segs (hi & lo paired)
#pragma unroll
        for (int i = 0; i < 2; i++) {
            int seg = tid + i * 256;
            int r  = seg >> 2;         // 0..127
            int s8 = seg & 3;
            uint32_t d = SWZ64(r * 64 + s8 * 16);
            size_t ga = (size_t)(row0 + r) * DIM + k0 + s8 * 8;
            cp16(st + RA_HI + d, Ahi + ga);
            cp16(st + RA_LO + d, Alo + ga);
        }
        // B: 1024 segs (hi & lo paired)
#pragma unroll
        for (int i = 0; i < 4; i++) {
            int seg = tid + i * 256;
            int r  = seg >> 2;         // 0..255
            int s8 = seg & 3;
            uint32_t d = SWZ64(r * 64 + s8 * 16);
            size_t gb = (size_t)(col0 + r) * DIM + k0 + s8 * 8;
            cp16(st + RB_HI + d, Bhi + gb);
            cp16(st + RB_LO + d, Blo + gb);
        }
        cp_commit();
    };

    issue(0); issue(1); issue(2);

    for (int c = 0; c < NCHUNK; c++) {
        cp_wait<2>();
        __syncthreads();
        const uint32_t st = sb + (uint32_t)(c % NSTAGE) * STAGE_BYTES;

#pragma unroll
        for (int ks = 0; ks < 2; ks++) {
            const int kb = ks * 32;    // byte offset of k16 step within 64B row

            uint32_t ahi[4][4], alo[4][4];
#pragma unroll
            for (int mi = 0; mi < 4; mi++) {
                uint32_t off = SWZ64((m_base + mi * 16 + a_row_in) * 64 + kb + a_kseg);
                ldsm_x4(ahi[mi], st + RA_HI + off);
                ldsm_x4(alo[mi], st + RA_LO + off);
            }
            uint32_t bhi[4][4], blo[4][4];
#pragma unroll
            for (int j2 = 0; j2 < 4; j2++) {
                uint32_t off = SWZ64((n_base + j2 * 16 + b_row_in) * 64 + kb + b_kseg);
                ldsm_x4(bhi[j2], st + RB_HI + off);
                ldsm_x4(blo[j2], st + RB_LO + off);
            }
            // Product-major: 32 independent accumulators between same-acc writes
#pragma unroll
            for (int mi = 0; mi < 4; mi++)
#pragma unroll
                for (int nj = 0; nj < 8; nj++)
                    mma16816(acc[mi][nj], ahi[mi],
                             bhi[nj >> 1][(nj & 1) * 2], bhi[nj >> 1][(nj & 1) * 2 + 1]);
#pragma unroll
            for (int mi = 0; mi < 4; mi++)
#pragma unroll
                for (int nj = 0; nj < 8; nj++)
                    mma16816(acc[mi][nj], ahi[mi],
                             blo[nj >> 1][(nj & 1) * 2], blo[nj >> 1][(nj & 1) * 2 + 1]);
#pragma unroll
            for (int mi = 0; mi < 4; mi++)
#pragma unroll
                for (int nj = 0; nj < 8; nj++)
                    mma16816(acc[mi][nj], alo[mi],
                             bhi[nj >> 1][(nj & 1) * 2], bhi[nj >> 1][(nj & 1) * 2 + 1]);
        }
        __syncthreads();
        if (c + NSTAGE < NCHUNK) issue(c + NSTAGE);
    }

    // Epilogue: add bias, store fp32
    const int rw = row0 + m_base;
    const int cw = col0 + n_base;
#pragma unroll
    for (int nj = 0; nj < 8; nj++) {
        int n = cw + nj * 8 + (lane & 3) * 2;
        float bx = __ldg(&bias[n]);
        float by = __ldg(&bias[n + 1]);
#pragma unroll
        for (int mi = 0; mi < 4; mi++) {
            int r = rw + mi * 16 + (lane >> 2);
            float2 v0 = make_float2(acc[mi][nj][0] + bx, acc[mi][nj][1] + by);
            float2 v1 = make_float2(acc[mi][nj][2] + bx, acc[mi][nj][3] + by);
            *(float2*)(C + (size_t)r * DIM + n)       = v0;
            *(float2*)(C + (size_t)(r + 8) * DIM + n) = v1;
        }
    }
}

// ---------------------------------------------------------------------------
// Per-token attention: RoPE(q,k) -> 16x16 scores -> softmax -> ctx.
// Writes scrambled ctx DIRECTLY as bf16 hi/lo for the O projection.
// Scramble: ctx[b,s,h,e] -> row h*128 + s/16, col (s%16)*64 + e
// ---------------------------------------------------------------------------
__global__ __launch_bounds__(256)
void attn_kernel(float* __restrict__ attn_out, int write_attn) {
    __shared__ float q[DIM], k[DIM], v[DIM], qr[DIM], kr[DIM];
    __shared__ float sc[HEADS * HEADS];

    int t   = blockIdx.x;
    int b   = t >> 11;
    int s   = t & (SEQ - 1);
    int tid = threadIdx.x;

    const float* qg = g_q + (size_t)t * DIM;
    const float* kg = g_k + (size_t)t * DIM;
    const float* vg = g_v + (size_t)t * DIM;

    for (int d = tid; d < DIM; d += 256) {
        q[d] = qg[d]; k[d] = kg[d]; v[d] = vg[d];
    }
    __syncthreads();

    for (int d = tid; d < DIM; d += 256) {
        int j = d & (HALF - 1);
        float c  = g_cos[s * HALF + j];
        float sn = g_sin[s * HALF + j];
        float rq = (d < HALF) ? -q[d + HALF] : q[d - HALF];
        float rk = (d < HALF) ? -k[d + HALF] : k[d - HALF];
        qr[d] = q[d] * c + rq * sn;
        kr[d] = k[d] * c + rk * sn;
    }
    __syncthreads();

    {
        int i = tid >> 4, j = tid & 15;
        float sum = 0.0f;
        const float* qp = &qr[i * HD];
        const float* kp = &kr[j * HD];
#pragma unroll
        for (int e = 0; e < HD; e++) sum += qp[e] * kp[e];
        sc[tid] = sum * 0.125f;
    }
    __syncthreads();

    if (tid < HEADS) {
        float m = -1e30f;
#pragma unroll
        for (int j = 0; j < HEADS; j++) m = fmaxf(m, sc[tid * HEADS + j]);
        float ev[HEADS];
        float ssum = 0.0f;
#pragma unroll
        for (int j = 0; j < HEADS; j++) {
            ev[j] = expf(sc[tid * HEADS + j] - m);
            ssum += ev[j];
        }
        float inv = 1.0f / ssum;
#pragma unroll
        for (int j = 0; j < HEADS; j++) sc[tid * HEADS + j] = ev[j] * inv;
    }
    __syncthreads();

    if (write_attn) {
        attn_out[(size_t)t * 256 + tid] = sc[tid];
    }

    for (int idx = tid; idx < DIM; idx += 256) {
        int i = idx >> 6;
        int e = idx & (HD - 1);
        float sum = 0.0f;
#pragma unroll
        for (int j = 0; j < HEADS; j++) sum += sc[i * HEADS + j] * v[j * HD + e];
        int r = i * (SEQ / HEADS) + (s >> 4);
        int c = ((s & 15) << 6) | e;
        size_t off = (size_t)b * SEQ * DIM + (size_t)r * DIM + c;
        __nv_bfloat16 h = __float2bfloat16(sum);
        g_xx_hi[off] = h;
        g_xx_lo[off] = __float2bfloat16(sum - __bfloat162float(h));
    }
}

// ---------------------------------------------------------------------------
// Host launcher. Launch order puts gemm_q at position 6 so ncu (-s 5 -c 1)
// captures the GEMM instead of a converter.
// ---------------------------------------------------------------------------
extern "C" void kernel_launch(void* const* d_in, const int* in_sizes, int n_in,
                              void* d_out, int out_size) {
    const float* inputs  = (const float*)d_in[0];
    const float* context = (const float*)d_in[1];
    const float* Wq = (const float*)d_in[2];
    const float* bq = (const float*)d_in[3];
    const float* Wk = (const float*)d_in[4];
    const float* bk = (const float*)d_in[5];
    const float* Wv = (const float*)d_in[6];
    const float* bv = (const float*)d_in[7];
    const float* Wo = (const float*)d_in[8];
    const float* bo = (const float*)d_in[9];
    float* out = (float*)d_out;

    cudaFuncSetAttribute(gemm_mma, cudaFuncAttributeMaxDynamicSharedMemorySize,
                         SMEM_TOTAL);

    float *pq, *pk, *pv;
    cudaGetSymbolAddress((void**)&pq, g_q);
    cudaGetSymbolAddress((void**)&pk, g_k);
    cudaGetSymbolAddress((void**)&pv, g_v);

    __nv_bfloat16 *in_hi, *in_lo, *cx_hi, *cx_lo, *xx_hi, *xx_lo;
    __nv_bfloat16 *wq_hi, *wq_lo, *wk_hi, *wk_lo, *wv_hi, *wv_lo, *wo_hi, *wo_lo;
    cudaGetSymbolAddress((void**)&in_hi, g_in_hi);
    cudaGetSymbolAddress((void**)&in_lo, g_in_lo);
    cudaGetSymbolAddress((void**)&cx_hi, g_cx_hi);
    cudaGetSymbolAddress((void**)&cx_lo, g_cx_lo);
    cudaGetSymbolAddress((void**)&xx_hi, g_xx_hi);
    cudaGetSymbolAddress((void**)&xx_lo, g_xx_lo);
    cudaGetSymbolAddress((void**)&wq_hi, g_wq_hi);
    cudaGetSymbolAddress((void**)&wq_lo, g_wq_lo);
    cudaGetSymbolAddress((void**)&wk_hi, g_wk_hi);
    cudaGetSymbolAddress((void**)&wk_lo, g_wk_lo);
    cudaGetSymbolAddress((void**)&wv_hi, g_wv_hi);
    cudaGetSymbolAddress((void**)&wv_lo, g_wv_lo);
    cudaGetSymbolAddress((void**)&wo_hi, g_wo_hi);
    cudaGetSymbolAddress((void**)&wo_lo, g_wo_lo);

    const int out_elems  = MTOK * DIM;
    const int attn_elems = MTOK * HEADS * HEADS;
    int write_attn = (out_size >= out_elems + attn_elems) ? 1 : 0;
    float* attn_out = out + out_elems;

    dim3 wgrid(32, 32), wblk(32, 8);
    dim3 ggrid(DIM / GN, MTOK / GM);   // (4, 32) = 128 CTAs

    // #1-2: RoPE tables
    rope_inv_kernel<<<1, 512>>>();
    rope_tab_kernel<<<(SEQ * HALF) / 256, 256>>>();
    // #3-5: converts needed for gemm_q
    convert_w_kernel<<<wgrid, wblk>>>(Wq, wq_hi, wq_lo);
    convert_act_kernel<<<(MTOK * DIM) / 1024, 256>>>(inputs,  in_hi, in_lo);
    convert_act_kernel<<<(MTOK * DIM) / 1024, 256>>>(context, cx_hi, cx_lo);
    // #6: Q projection  <-- ncu capture slot
    gemm_mma<<<ggrid, 256, SMEM_TOTAL>>>(in_hi, in_lo, wq_hi, wq_lo, bq, pq);
    // #7-10: K, V projections
    convert_w_kernel<<<wgrid, wblk>>>(Wk, wk_hi, wk_lo);
    gemm_mma<<<ggrid, 256, SMEM_TOTAL>>>(cx_hi, cx_lo, wk_hi, wk_lo, bk, pk);
    convert_w_kernel<<<wgrid, wblk>>>(Wv, wv_hi, wv_lo);
    gemm_mma<<<ggrid, 256, SMEM_TOTAL>>>(cx_hi, cx_lo, wv_hi, wv_lo, bv, pv);
    // #11: RoPE + per-token head attention + scramble (writes bf16 hi/lo)
    attn_kernel<<<MTOK, 256>>>(attn_out, write_attn);
    // #12-13: O projection
    convert_w_kernel<<<wgrid, wblk>>>(Wo, wo_hi, wo_lo);
    gemm_mma<<<ggrid, 256, SMEM_TOTAL>>>(xx_hi, xx_lo, wo_hi, wo_lo, bo, out);
}

// round 7
// speedup vs baseline: 1.0459x; 1.0459x over previous
#include <cuda_runtime.h>
#include <cuda_bf16.h>
#include <stdint.h>
#include <math.h>

// Problem constants
#define BATCH 2
#define SEQ   2048
#define DIM   1024
#define HEADS 16
#define HD    64
#define MTOK  (BATCH * SEQ)            // 4096 tokens
#define HALF  (DIM / 2)                // 512

// tf32 GEMM tiling: CTA 128x128, 8 warps (2Mx4N), warp 64x32, K-chunk 32 floats
#define GM 128
#define GN 128
#define GKC 32
#define NCHUNK (DIM / GKC)             // 32
#define NSTAGE 3
#define RSTRIDE 144                     // padded row stride bytes (36 floats)
#define RA 0
#define RB (128 * RSTRIDE)              // 18432
#define STAGE_BYTES (2 * 128 * RSTRIDE) // 36864
#define SMEM_TOTAL (NSTAGE * STAGE_BYTES) // 110592 -> 2 CTAs/SM

// ---------------------------------------------------------------------------
// Device scratch (no cudaMalloc allowed)
// ---------------------------------------------------------------------------
__device__ float g_q[MTOK * DIM];
__device__ float g_k[MTOK * DIM];
__device__ float g_v[MTOK * DIM];
__device__ float g_xx[MTOK * DIM];       // scrambled ctx (rna-rounded)
__device__ float g_cos[SEQ * HALF];
__device__ float g_sin[SEQ * HALF];
__device__ float g_invf[HALF];

__device__ float g_wq[DIM * DIM];        // transposed [N][K], rna-rounded
__device__ float g_wk[DIM * DIM];
__device__ float g_wv[DIM * DIM];
__device__ float g_wo[DIM * DIM];

// ---------------------------------------------------------------------------
// Helpers
// ---------------------------------------------------------------------------
__device__ __forceinline__ uint32_t smem_u32(const void* p) {
    uint32_t a;
    asm("{ .reg .u64 t; cvta.to.shared.u64 t, %1; cvt.u32.u64 %0, t; }"
        : "=r"(a) : "l"(p));
    return a;
}

__device__ __forceinline__ void cp16(uint32_t smem, const void* g) {
    asm volatile("cp.async.cg.shared.global [%0], [%1], 16;" :: "r"(smem), "l"(g));
}
__device__ __forceinline__ void cp_commit() {
    asm volatile("cp.async.commit_group;" ::: "memory");
}
template <int N>
__device__ __forceinline__ void cp_wait() {
    asm volatile("cp.async.wait_group %0;" :: "n"(N) : "memory");
}

__device__ __forceinline__ float lds_f32(uint32_t addr) {
    float v;
    asm volatile("ld.shared.f32 %0, [%1];" : "=f"(v) : "r"(addr));
    return v;
}
__device__ __forceinline__ uint32_t lds_u32(uint32_t addr) {
    uint32_t v;
    asm volatile("ld.shared.b32 %0, [%1];" : "=r"(v) : "r"(addr));
    return v;
}
__device__ __forceinline__ uint32_t f2tf32(float x) {
    uint32_t u;
    asm("cvt.rna.tf32.f32 %0, %1;" : "=r"(u) : "f"(x));
    return u;
}
__device__ __forceinline__ float rna_f32(float x) {
    uint32_t u;
    asm("cvt.rna.tf32.f32 %0, %1;" : "=r"(u) : "f"(x));
    return __uint_as_float(u);
}

__device__ __forceinline__ void mma_tf32(float* d, const uint32_t* a,
                                         uint32_t b0, uint32_t b1) {
    asm volatile(
        "mma.sync.aligned.m16n8k8.row.col.f32.tf32.tf32.f32 "
        "{%0,%1,%2,%3}, {%4,%5,%6,%7}, {%8,%9}, {%0,%1,%2,%3};"
        : "+f"(d[0]), "+f"(d[1]), "+f"(d[2]), "+f"(d[3])
        : "r"(a[0]), "r"(a[1]), "r"(a[2]), "r"(a[3]), "r"(b0), "r"(b1));
}

// ---------------------------------------------------------------------------
// RoPE tables
// ---------------------------------------------------------------------------
__global__ void rope_inv_kernel() {
    int j = threadIdx.x;
    if (j < HALF) {
        double inv = exp(-((double)(2 * j) / (double)DIM) * log(10000.0));
        g_invf[j] = (float)inv;
    }
}

__global__ void rope_tab_kernel() {
    int idx = blockIdx.x * 256 + threadIdx.x;
    int s = idx >> 9;
    int j = idx & (HALF - 1);
    float arg = (float)s * g_invf[j];
    float sn, cs;
    sincosf(arg, &sn, &cs);
    g_cos[idx] = cs;
    g_sin[idx] = sn;
}

// ---------------------------------------------------------------------------
// W [K][N] fp32 -> transposed [N][K] fp32, RNA-rounded to tf32 precision
// ---------------------------------------------------------------------------
__global__ void convert_w_kernel(const float* __restrict__ W,
                                 float* __restrict__ Wt) {
    __shared__ float t[32][33];
    int k0 = blockIdx.y * 32, n0 = blockIdx.x * 32;
    int tx = threadIdx.x, ty = threadIdx.y;   // 32 x 8
#pragma unroll
    for (int i = 0; i < 32; i += 8)
        t[ty + i][tx] = W[(size_t)(k0 + ty + i) * DIM + n0 + tx];
    __syncthreads();
#pragma unroll
    for (int i = 0; i < 32; i += 8) {
        float x = t[tx][ty + i];              // W[k0+tx][n0+ty+i]
        Wt[(size_t)(n0 + ty + i) * DIM + k0 + tx] = rna_f32(x);
    }
}

// ---------------------------------------------------------------------------
// tf32 single-product GEMM:  C[M,N] = rna(A) @ rna(B)^T + bias
// A: [m][k] fp32 raw (rounded in-register).  B: [n][k] fp32 pre-rounded.
// CTA 128x128, warp 64x32, K-chunk 32 floats (128B data + 16B pad per row).
// Padded 144B rows -> conflict-free LDS with immediate offsets (no swizzle).
// ---------------------------------------------------------------------------
__global__ void __launch_bounds__(256, 2)
gemm_tf32(const float* __restrict__ A, const float* __restrict__ B,
          const float* __restrict__ bias, float* __restrict__ C) {
    extern __shared__ __align__(1024) char smem[];
    const int tid  = threadIdx.x;
    const int wid  = tid >> 5;
    const int lane = tid & 31;
    const int row0 = blockIdx.y * GM;
    const int col0 = blockIdx.x * GN;
    const uint32_t sb = smem_u32(smem);

    const int wm = wid >> 2;            // 0..1
    const int wn = wid & 3;             // 0..3
    const int m_base = wm * 64;
    const int n_base = wn * 32;

    float acc[4][4][4];
#pragma unroll
    for (int i = 0; i < 4; i++)
#pragma unroll
        for (int j = 0; j < 4; j++)
#pragma unroll
            for (int e = 0; e < 4; e++) acc[i][j][e] = 0.0f;

    // --- chunk loader: A rows 128 x 8 segs, B rows 128 x 8 segs (16B each) ---
    auto issue = [&](int c) {
        const uint32_t st = sb + (uint32_t)(c % NSTAGE) * STAGE_BYTES;
        const int k0 = c * GKC;
#pragma unroll
        for (int i = 0; i < 4; i++) {
            int seg = tid + i * 256;
            int r  = seg >> 3;
            int s8 = seg & 7;
            cp16(st + RA + r * RSTRIDE + s8 * 16,
                 A + (size_t)(row0 + r) * DIM + k0 + s8 * 4);
        }
#pragma unroll
        for (int i = 0; i < 4; i++) {
            int seg = tid + i * 256;
            int r  = seg >> 3;
            int s8 = seg & 7;
            cp16(st + RB + r * RSTRIDE + s8 * 16,
                 B + (size_t)(col0 + r) * DIM + k0 + s8 * 4);
        }
        cp_commit();
    };

    issue(0); issue(1); issue(2);

    for (int c = 0; c < NCHUNK; c++) {
        cp_wait<2>();
        __syncthreads();
        const uint32_t st = sb + (uint32_t)(c % NSTAGE) * STAGE_BYTES;
        // per-lane fragment bases: row = lane/4, col = lane%4
        const uint32_t abase = st + RA + (m_base + (lane >> 2)) * RSTRIDE + (lane & 3) * 4;
        const uint32_t bbase = st + RB + (n_base + (lane >> 2)) * RSTRIDE + (lane & 3) * 4;

#pragma unroll
        for (int ks = 0; ks < 4; ks++) {
            const int kb = ks * 32;     // k8 step = 8 floats = 32 bytes

            uint32_t a[4][4];
#pragma unroll
            for (int mi = 0; mi < 4; mi++) {
                uint32_t base = abase + mi * (16 * RSTRIDE) + kb;
                a[mi][0] = f2tf32(lds_f32(base));
                a[mi][1] = f2tf32(lds_f32(base + 8 * RSTRIDE));
                a[mi][2] = f2tf32(lds_f32(base + 16));
                a[mi][3] = f2tf32(lds_f32(base + 8 * RSTRIDE + 16));
            }
            uint32_t b[4][2];
#pragma unroll
            for (int nj = 0; nj < 4; nj++) {
                uint32_t base = bbase + nj * (8 * RSTRIDE) + kb;
                b[nj][0] = lds_u32(base);
                b[nj][1] = lds_u32(base + 16);
            }
#pragma unroll
            for (int mi = 0; mi < 4; mi++)
#pragma unroll
                for (int nj = 0; nj < 4; nj++)
                    mma_tf32(acc[mi][nj], a[mi], b[nj][0], b[nj][1]);
        }
        __syncthreads();
        if (c + NSTAGE < NCHUNK) issue(c + NSTAGE);
    }

    // Epilogue: add bias, store fp32
    const int rw = row0 + m_base;
    const int cw = col0 + n_base;
#pragma unroll
    for (int nj = 0; nj < 4; nj++) {
        int n = cw + nj * 8 + (lane & 3) * 2;
        float bx = __ldg(&bias[n]);
        float by = __ldg(&bias[n + 1]);
#pragma unroll
        for (int mi = 0; mi < 4; mi++) {
            int r = rw + mi * 16 + (lane >> 2);
            float2 v0 = make_float2(acc[mi][nj][0] + bx, acc[mi][nj][1] + by);
            float2 v1 = make_float2(acc[mi][nj][2] + bx, acc[mi][nj][3] + by);
            *(float2*)(C + (size_t)r * DIM + n)       = v0;
            *(float2*)(C + (size_t)(r + 8) * DIM + n) = v1;
        }
    }
}

// ---------------------------------------------------------------------------
// Per-token attention: RoPE(q,k) -> 16x16 scores -> softmax -> ctx.
// Writes scrambled ctx as RNA-rounded fp32 (ready as tf32 GEMM A operand).
// Scramble: ctx[b,s,h,e] -> row h*128 + s/16, col (s%16)*64 + e
// ---------------------------------------------------------------------------
__global__ __launch_bounds__(256)
void attn_kernel(float* __restrict__ attn_out, int write_attn) {
    __shared__ float q[DIM], k[DIM], v[DIM], qr[DIM], kr[DIM];
    __shared__ float sc[HEADS * HEADS];

    int t   = blockIdx.x;
    int b   = t >> 11;
    int s   = t & (SEQ - 1);
    int tid = threadIdx.x;

    const float* qg = g_q + (size_t)t * DIM;
    const float* kg = g_k + (size_t)t * DIM;
    const float* vg = g_v + (size_t)t * DIM;

    for (int d = tid; d < DIM; d += 256) {
        q[d] = qg[d]; k[d] = kg[d]; v[d] = vg[d];
    }
    __syncthreads();

    for (int d = tid; d < DIM; d += 256) {
        int j = d & (HALF - 1);
        float c  = g_cos[s * HALF + j];
        float sn = g_sin[s * HALF + j];
        float rq = (d < HALF) ? -q[d + HALF] : q[d - HALF];
        float rk = (d < HALF) ? -k[d + HALF] : k[d - HALF];
        qr[d] = q[d] * c + rq * sn;
        kr[d] = k[d] * c + rk * sn;
    }
    __syncthreads();

    {
        int i = tid >> 4, j = tid & 15;
        float sum = 0.0f;
        const float* qp = &qr[i * HD];
        const float* kp = &kr[j * HD];
#pragma unroll
        for (int e = 0; e < HD; e++) sum += qp[e] * kp[e];
        sc[tid] = sum * 0.125f;
    }
    __syncthreads();

    if (tid < HEADS) {
        float m = -1e30f;
#pragma unroll
        for (int j = 0; j < HEADS; j++) m = fmaxf(m, sc[tid * HEADS + j]);
        float ev[HEADS];
        float ssum = 0.0f;
#pragma unroll
        for (int j = 0; j < HEADS; j++) {
            ev[j] = expf(sc[tid * HEADS + j] - m);
            ssum += ev[j];
        }
        float inv = 1.0f / ssum;
#pragma unroll
        for (int j = 0; j < HEADS; j++) sc[tid * HEADS + j] = ev[j] * inv;
    }
    __syncthreads();

    if (write_attn) {
        attn_out[(size_t)t * 256 + tid] = sc[tid];
    }

    for (int idx = tid; idx < DIM; idx += 256) {
        int i = idx >> 6;
        int e = idx & (HD - 1);
        float sum = 0.0f;
#pragma unroll
        for (int j = 0; j < HEADS; j++) sum += sc[i * HEADS + j] * v[j * HD + e];
        int r = i * (SEQ / HEADS) + (s >> 4);
        int c = ((s & 15) << 6) | e;
        size_t off = (size_t)b * SEQ * DIM + (size_t)r * DIM + c;
        g_xx[off] = rna_f32(sum);
    }
}

// ---------------------------------------------------------------------------
// Host launcher. Launches #5 and #6 are both GEMMs so either ncu indexing
// captures a GEMM profile.
// ---------------------------------------------------------------------------
extern "C" void kernel_launch(void* const* d_in, const int* in_sizes, int n_in,
                              void* d_out, int out_size) {
    const float* inputs  = (const float*)d_in[0];
    const float* context = (const float*)d_in[1];
    const float* Wq = (const float*)d_in[2];
    const float* bq = (const float*)d_in[3];
    const float* Wk = (const float*)d_in[4];
    const float* bk = (const float*)d_in[5];
    const float* Wv = (const float*)d_in[6];
    const float* bv = (const float*)d_in[7];
    const float* Wo = (const float*)d_in[8];
    const float* bo = (const float*)d_in[9];
    float* out = (float*)d_out;

    cudaFuncSetAttribute(gemm_tf32, cudaFuncAttributeMaxDynamicSharedMemorySize,
                         SMEM_TOTAL);

    float *pq, *pk, *pv, *pxx, *pwq, *pwk, *pwv, *pwo;
    cudaGetSymbolAddress((void**)&pq,  g_q);
    cudaGetSymbolAddress((void**)&pk,  g_k);
    cudaGetSymbolAddress((void**)&pv,  g_v);
    cudaGetSymbolAddress((void**)&pxx, g_xx);
    cudaGetSymbolAddress((void**)&pwq, g_wq);
    cudaGetSymbolAddress((void**)&pwk, g_wk);
    cudaGetSymbolAddress((void**)&pwv, g_wv);
    cudaGetSymbolAddress((void**)&pwo, g_wo);

    const int out_elems  = MTOK * DIM;
    const int attn_elems = MTOK * HEADS * HEADS;
    int write_attn = (out_size >= out_elems + attn_elems) ? 1 : 0;
    float* attn_out = out + out_elems;

    dim3 wgrid(32, 32), wblk(32, 8);
    dim3 ggrid(DIM / GN, MTOK / GM);   // (8, 32) = 256 CTAs

    // #1-4: weight transpose + tf32 rounding
    convert_w_kernel<<<wgrid, wblk>>>(Wq, pwq);
    convert_w_kernel<<<wgrid, wblk>>>(Wk, pwk);
    convert_w_kernel<<<wgrid, wblk>>>(Wv, pwv);
    convert_w_kernel<<<wgrid, wblk>>>(Wo, pwo);
    // #5-7: Q/K/V projections (tf32 tensor cores, raw fp32 activations)
    gemm_tf32<<<ggrid, 256, SMEM_TOTAL>>>(inputs,  pwq, bq, pq);
    gemm_tf32<<<ggrid, 256, SMEM_TOTAL>>>(context, pwk, bk, pk);
    gemm_tf32<<<ggrid, 256, SMEM_TOTAL>>>(context, pwv, bv, pv);
    // #8-9: RoPE tables (only needed by attn)
    rope_inv_kernel<<<1, 512>>>();
    rope_tab_kernel<<<(SEQ * HALF) / 256, 256>>>();
    // #10: RoPE + per-token head attention + scramble
    attn_kernel<<<MTOK, 256>>>(attn_out, write_attn);
    // #11: O projection
    gemm_tf32<<<ggrid, 256, SMEM_TOTAL>>>(pxx, pwo, bo, out);
}

// round 8
// speedup vs baseline: 1.1518x; 1.1013x over previous
#include <cuda_runtime.h>
#include <stdint.h>
#include <math.h>

// Problem constants
#define BATCH 2
#define SEQ   2048
#define DIM   1024
#define HEADS 16
#define HD    64
#define MTOK  (BATCH * SEQ)            // 4096 tokens
#define HALF  (DIM / 2)                // 512

// tf32 GEMM tiling: CTA 128x256, 8 warps (2Mx4N), warp tile 64x64, K-chunk 32
#define GM 128
#define GN 256
#define GKC 32
#define NCHUNK (DIM / GKC)             // 32
#define NSTAGE 3
#define RSTRIDE 144                     // padded row stride bytes (36 floats)
#define RA 0
#define RB (128 * RSTRIDE)              // 18432
#define STAGE_BYTES ((128 + 256) * RSTRIDE) // 55296
#define SMEM_TOTAL (NSTAGE * STAGE_BYTES)   // 165888 -> 1 CTA/SM

// ---------------------------------------------------------------------------
// Device scratch (no cudaMalloc allowed)
// ---------------------------------------------------------------------------
__device__ float g_q[MTOK * DIM];
__device__ float g_k[MTOK * DIM];
__device__ float g_v[MTOK * DIM];
__device__ float g_xx[MTOK * DIM];       // scrambled ctx (rna-rounded)
__device__ float g_cos[SEQ * HALF];
__device__ float g_sin[SEQ * HALF];
__device__ float g_invf[HALF];

__device__ float g_wq[DIM * DIM];        // transposed [N][K], rna-rounded
__device__ float g_wk[DIM * DIM];
__device__ float g_wv[DIM * DIM];
__device__ float g_wo[DIM * DIM];

// ---------------------------------------------------------------------------
// Helpers
// ---------------------------------------------------------------------------
__device__ __forceinline__ uint32_t smem_u32(const void* p) {
    uint32_t a;
    asm("{ .reg .u64 t; cvta.to.shared.u64 t, %1; cvt.u32.u64 %0, t; }"
        : "=r"(a) : "l"(p));
    return a;
}

__device__ __forceinline__ void cp16(uint32_t smem, const void* g) {
    asm volatile("cp.async.cg.shared.global [%0], [%1], 16;" :: "r"(smem), "l"(g));
}
__device__ __forceinline__ void cp_commit() {
    asm volatile("cp.async.commit_group;" ::: "memory");
}
template <int N>
__device__ __forceinline__ void cp_wait() {
    asm volatile("cp.async.wait_group %0;" :: "n"(N) : "memory");
}

__device__ __forceinline__ float lds_f32(uint32_t addr) {
    float v;
    asm volatile("ld.shared.f32 %0, [%1];" : "=f"(v) : "r"(addr));
    return v;
}
__device__ __forceinline__ uint32_t lds_u32(uint32_t addr) {
    uint32_t v;
    asm volatile("ld.shared.b32 %0, [%1];" : "=r"(v) : "r"(addr));
    return v;
}
__device__ __forceinline__ uint32_t f2tf32(float x) {
    uint32_t u;
    asm("cvt.rna.tf32.f32 %0, %1;" : "=r"(u) : "f"(x));
    return u;
}
__device__ __forceinline__ float rna_f32(float x) {
    uint32_t u;
    asm("cvt.rna.tf32.f32 %0, %1;" : "=r"(u) : "f"(x));
    return __uint_as_float(u);
}

__device__ __forceinline__ void mma_tf32(float* d, const uint32_t* a,
                                         uint32_t b0, uint32_t b1) {
    asm volatile(
        "mma.sync.aligned.m16n8k8.row.col.f32.tf32.tf32.f32 "
        "{%0,%1,%2,%3}, {%4,%5,%6,%7}, {%8,%9}, {%0,%1,%2,%3};"
        : "+f"(d[0]), "+f"(d[1]), "+f"(d[2]), "+f"(d[3])
        : "r"(a[0]), "r"(a[1]), "r"(a[2]), "r"(a[3]), "r"(b0), "r"(b1));
}

// ---------------------------------------------------------------------------
// RoPE tables
// ---------------------------------------------------------------------------
__global__ void rope_inv_kernel() {
    int j = threadIdx.x;
    if (j < HALF) {
        double inv = exp(-((double)(2 * j) / (double)DIM) * log(10000.0));
        g_invf[j] = (float)inv;
    }
}

__global__ void rope_tab_kernel() {
    int idx = blockIdx.x * 256 + threadIdx.x;
    int s = idx >> 9;
    int j = idx & (HALF - 1);
    float arg = (float)s * g_invf[j];
    float sn, cs;
    sincosf(arg, &sn, &cs);
    g_cos[idx] = cs;
    g_sin[idx] = sn;
}

// ---------------------------------------------------------------------------
// All 4 weight transposes in ONE launch. blockIdx.z selects the matrix.
// W [K][N] fp32 -> transposed [N][K] fp32, RNA-rounded to tf32 precision.
// ---------------------------------------------------------------------------
__global__ void convert_w4_kernel(const float* __restrict__ W0,
                                  const float* __restrict__ W1,
                                  const float* __restrict__ W2,
                                  const float* __restrict__ W3,
                                  float* __restrict__ T0, float* __restrict__ T1,
                                  float* __restrict__ T2, float* __restrict__ T3) {
    __shared__ float t[32][33];
    const float* W = (blockIdx.z == 0) ? W0 : (blockIdx.z == 1) ? W1
                   : (blockIdx.z == 2) ? W2 : W3;
    float* T = (blockIdx.z == 0) ? T0 : (blockIdx.z == 1) ? T1
             : (blockIdx.z == 2) ? T2 : T3;
    int k0 = blockIdx.y * 32, n0 = blockIdx.x * 32;
    int tx = threadIdx.x, ty = threadIdx.y;   // 32 x 8
#pragma unroll
    for (int i = 0; i < 32; i += 8)
        t[ty + i][tx] = W[(size_t)(k0 + ty + i) * DIM + n0 + tx];
    __syncthreads();
#pragma unroll
    for (int i = 0; i < 32; i += 8) {
        float x = t[tx][ty + i];              // W[k0+tx][n0+ty+i]
        T[(size_t)(n0 + ty + i) * DIM + k0 + tx] = rna_f32(x);
    }
}

// ---------------------------------------------------------------------------
// tf32 single-product GEMM:  C[M,N] = rna(A) @ rna(B)^T + bias
// CTA 128x256, 8 warps (2Mx4N), warp tile 64x64 -> 0.125 operand-bytes/MAC
// through the smem crossbar (vs 0.1875 for 64x32).
// Padded 144B rows -> conflict-free scalar LDS with immediate offsets.
// ---------------------------------------------------------------------------
__global__ void __launch_bounds__(256, 1)
gemm_tf32(const float* __restrict__ A, const float* __restrict__ B,
          const float* __restrict__ bias, float* __restrict__ C) {
    extern __shared__ __align__(1024) char smem[];
    const int tid  = threadIdx.x;
    const int wid  = tid >> 5;
    const int lane = tid & 31;
    const int row0 = blockIdx.y * GM;
    const int col0 = blockIdx.x * GN;
    const uint32_t sb = smem_u32(smem);

    const int wm = wid >> 2;            // 0..1
    const int wn = wid & 3;             // 0..3
    const int m_base = wm * 64;
    const int n_base = wn * 64;

    float acc[4][8][4];
#pragma unroll
    for (int i = 0; i < 4; i++)
#pragma unroll
        for (int j = 0; j < 8; j++)
#pragma unroll
            for (int e = 0; e < 4; e++) acc[i][j][e] = 0.0f;

    // --- chunk loader: A 128 rows x 8 segs, B 256 rows x 8 segs (16B each) ---
    auto issue = [&](int c) {
        const uint32_t st = sb + (uint32_t)(c % NSTAGE) * STAGE_BYTES;
        const int k0 = c * GKC;
#pragma unroll
        for (int i = 0; i < 4; i++) {
            int seg = tid + i * 256;
            int r  = seg >> 3;
            int s8 = seg & 7;
            cp16(st + RA + r * RSTRIDE + s8 * 16,
                 A + (size_t)(row0 + r) * DIM + k0 + s8 * 4);
        }
#pragma unroll
        for (int i = 0; i < 8; i++) {
            int seg = tid + i * 256;
            int r  = seg >> 3;
            int s8 = seg & 7;
            cp16(st + RB + r * RSTRIDE + s8 * 16,
                 B + (size_t)(col0 + r) * DIM + k0 + s8 * 4);
        }
        cp_commit();
    };

    issue(0); issue(1); issue(2);

    for (int c = 0; c < NCHUNK; c++) {
        cp_wait<2>();
        __syncthreads();
        const uint32_t st = sb + (uint32_t)(c % NSTAGE) * STAGE_BYTES;
        const uint32_t abase = st + RA + (m_base + (lane >> 2)) * RSTRIDE + (lane & 3) * 4;
        const uint32_t bbase = st + RB + (n_base + (lane >> 2)) * RSTRIDE + (lane & 3) * 4;

#pragma unroll
        for (int ks = 0; ks < 4; ks++) {
            const int kb = ks * 32;     // k8 step = 8 floats = 32 bytes

            uint32_t a[4][4];
#pragma unroll
            for (int mi = 0; mi < 4; mi++) {
                uint32_t base = abase + mi * (16 * RSTRIDE) + kb;
                a[mi][0] = f2tf32(lds_f32(base));
                a[mi][1] = f2tf32(lds_f32(base + 8 * RSTRIDE));
                a[mi][2] = f2tf32(lds_f32(base + 16));
                a[mi][3] = f2tf32(lds_f32(base + 8 * RSTRIDE + 16));
            }
            uint32_t b[8][2];
#pragma unroll
            for (int nj = 0; nj < 8; nj++) {
                uint32_t base = bbase + nj * (8 * RSTRIDE) + kb;
                b[nj][0] = lds_u32(base);
                b[nj][1] = lds_u32(base + 16);
            }
#pragma unroll
            for (int mi = 0; mi < 4; mi++)
#pragma unroll
                for (int nj = 0; nj < 8; nj++)
                    mma_tf32(acc[mi][nj], a[mi], b[nj][0], b[nj][1]);
        }
        __syncthreads();
        if (c + NSTAGE < NCHUNK) issue(c + NSTAGE);
    }

    // Epilogue: add bias, store fp32
    const int rw = row0 + m_base;
    const int cw = col0 + n_base;
#pragma unroll
    for (int nj = 0; nj < 8; nj++) {
        int n = cw + nj * 8 + (lane & 3) * 2;
        float bx = __ldg(&bias[n]);
        float by = __ldg(&bias[n + 1]);
#pragma unroll
        for (int mi = 0; mi < 4; mi++) {
            int r = rw + mi * 16 + (lane >> 2);
            float2 v0 = make_float2(acc[mi][nj][0] + bx, acc[mi][nj][1] + by);
            float2 v1 = make_float2(acc[mi][nj][2] + bx, acc[mi][nj][3] + by);
            *(float2*)(C + (size_t)r * DIM + n)       = v0;
            *(float2*)(C + (size_t)(r + 8) * DIM + n) = v1;
        }
    }
}

// ---------------------------------------------------------------------------
// Per-token attention: RoPE(q,k) -> 16x16 scores -> softmax -> ctx.
// Writes scrambled ctx as RNA-rounded fp32 (ready as tf32 GEMM A operand).
// Scramble: ctx[b,s,h,e] -> row h*128 + s/16, col (s%16)*64 + e
// ---------------------------------------------------------------------------
__global__ __launch_bounds__(256)
void attn_kernel(float* __restrict__ attn_out, int write_attn) {
    __shared__ float q[DIM], k[DIM], v[DIM], qr[DIM], kr[DIM];
    __shared__ float sc[HEADS * HEADS];

    int t   = blockIdx.x;
    int b   = t >> 11;
    int s   = t & (SEQ - 1);
    int tid = threadIdx.x;

    const float* qg = g_q + (size_t)t * DIM;
    const float* kg = g_k + (size_t)t * DIM;
    const float* vg = g_v + (size_t)t * DIM;

    for (int d = tid; d < DIM; d += 256) {
        q[d] = qg[d]; k[d] = kg[d]; v[d] = vg[d];
    }
    __syncthreads();

    for (int d = tid; d < DIM; d += 256) {
        int j = d & (HALF - 1);
        float c  = g_cos[s * HALF + j];
        float sn = g_sin[s * HALF + j];
        float rq = (d < HALF) ? -q[d + HALF] : q[d - HALF];
        float rk = (d < HALF) ? -k[d + HALF] : k[d - HALF];
        qr[d] = q[d] * c + rq * sn;
        kr[d] = k[d] * c + rk * sn;
    }
    __syncthreads();

    {
        int i = tid >> 4, j = tid & 15;
        float sum = 0.0f;
        const float* qp = &qr[i * HD];
        const float* kp = &kr[j * HD];
#pragma unroll
        for (int e = 0; e < HD; e++) sum += qp[e] * kp[e];
        sc[tid] = sum * 0.125f;
    }
    __syncthreads();

    if (tid < HEADS) {
        float m = -1e30f;
#pragma unroll
        for (int j = 0; j < HEADS; j++) m = fmaxf(m, sc[tid * HEADS + j]);
        float ev[HEADS];
        float ssum = 0.0f;
#pragma unroll
        for (int j = 0; j < HEADS; j++) {
            ev[j] = expf(sc[tid * HEADS + j] - m);
            ssum += ev[j];
        }
        float inv = 1.0f / ssum;
#pragma unroll
        for (int j = 0; j < HEADS; j++) sc[tid * HEADS + j] = ev[j] * inv;
    }
    __syncthreads();

    if (write_attn) {
        attn_out[(size_t)t * 256 + tid] = sc[tid];
    }

    for (int idx = tid; idx < DIM; idx += 256) {
        int i = idx >> 6;
        int e = idx & (HD - 1);
        float sum = 0.0f;
#pragma unroll
        for (int j = 0; j < HEADS; j++) sum += sc[i * HEADS + j] * v[j * HD + e];
        int r = i * (SEQ / HEADS) + (s >> 4);
        int c = ((s & 15) << 6) | e;
        size_t off = (size_t)b * SEQ * DIM + (size_t)r * DIM + c;
        g_xx[off] = rna_f32(sum);
    }
}

// ---------------------------------------------------------------------------
// Host launcher. Launches #4, #5, #6 are all GEMMs so the ncu capture slot
// (skip-5) lands on a GEMM regardless of off-by-one/harness-launch offsets.
// ---------------------------------------------------------------------------
extern "C" void kernel_launch(void* const* d_in, const int* in_sizes, int n_in,
                              void* d_out, int out_size) {
    const float* inputs  = (const float*)d_in[0];
    const float* context = (const float*)d_in[1];
    const float* Wq = (const float*)d_in[2];
    const float* bq = (const float*)d_in[3];
    const float* Wk = (const float*)d_in[4];
    const float* bk = (const float*)d_in[5];
    const float* Wv = (const float*)d_in[6];
    const float* bv = (const float*)d_in[7];
    const float* Wo = (const float*)d_in[8];
    const float* bo = (const float*)d_in[9];
    float* out = (float*)d_out;

    cudaFuncSetAttribute(gemm_tf32, cudaFuncAttributeMaxDynamicSharedMemorySize,
                         SMEM_TOTAL);

    float *pq, *pk, *pv, *pxx, *pwq, *pwk, *pwv, *pwo;
    cudaGetSymbolAddress((void**)&pq,  g_q);
    cudaGetSymbolAddress((void**)&pk,  g_k);
    cudaGetSymbolAddress((void**)&pv,  g_v);
    cudaGetSymbolAddress((void**)&pxx, g_xx);
    cudaGetSymbolAddress((void**)&pwq, g_wq);
    cudaGetSymbolAddress((void**)&pwk, g_wk);
    cudaGetSymbolAddress((void**)&pwv, g_wv);
    cudaGetSymbolAddress((void**)&pwo, g_wo);

    const int out_elems  = MTOK * DIM;
    const int attn_elems = MTOK * HEADS * HEADS;
    int write_attn = (out_size >= out_elems + attn_elems) ? 1 : 0;
    float* attn_out = out + out_elems;

    dim3 ggrid(DIM / GN, MTOK / GM);   // (4, 32) = 128 CTAs

    // #1: all weight transposes (one launch)
    convert_w4_kernel<<<dim3(32, 32, 4), dim3(32, 8)>>>(Wq, Wk, Wv, Wo,
                                                        pwq, pwk, pwv, pwo);
    // #2-3: RoPE tables
    rope_inv_kernel<<<1, 512>>>();
    rope_tab_kernel<<<(SEQ * HALF) / 256, 256>>>();
    // #4-6: Q/K/V projections  <-- ncu capture window
    gemm_tf32<<<ggrid, 256, SMEM_TOTAL>>>(inputs,  pwq, bq, pq);
    gemm_tf32<<<ggrid, 256, SMEM_TOTAL>>>(context, pwk, bk, pk);
    gemm_tf32<<<ggrid, 256, SMEM_TOTAL>>>(context, pwv, bv, pv);
    // #7: RoPE + per-token head attention + scramble
    attn_kernel<<<MTOK, 256>>>(attn_out, write_attn);
    // #8: O projection
    gemm_tf32<<<ggrid, 256, SMEM_TOTAL>>>(pxx, pwo, bo, out);
}

// round 9
// speedup vs baseline: 1.3387x; 1.1622x over previous
#include <cuda_runtime.h>
#include <stdint.h>
#include <math.h>

// Problem constants
#define BATCH 2
#define SEQ   2048
#define DIM   1024
#define HEADS 16
#define HD    64
#define MTOK  (BATCH * SEQ)            // 4096 tokens
#define HALF  (DIM / 2)                // 512

// tf32 GEMM tiling: CTA 128x256, 8 warps (2Mx4N), warp tile 64x64, K-chunk 32
#define GM 128
#define GN 256
#define GKC 32
#define NCHUNK (DIM / GKC)             // 32
#define NSTAGE 3
#define RSTRIDE 144                     // padded row stride bytes (36 floats)
#define RA 0
#define RB (128 * RSTRIDE)              // 18432
#define STAGE_BYTES ((128 + 256) * RSTRIDE) // 55296
#define SMEM_TOTAL (NSTAGE * STAGE_BYTES)   // 165888

// ---------------------------------------------------------------------------
// Device scratch (no cudaMalloc allowed)
// ---------------------------------------------------------------------------
__device__ float g_q[MTOK * DIM];
__device__ float g_k[MTOK * DIM];
__device__ float g_v[MTOK * DIM];
__device__ float g_xx[MTOK * DIM];       // scrambled ctx (rna-rounded)
__device__ float g_xa[MTOK * DIM];       // rna(inputs)
__device__ float g_xc[MTOK * DIM];       // rna(context)
__device__ float g_cos[SEQ * HALF];
__device__ float g_sin[SEQ * HALF];
__device__ float g_invf[HALF];

__device__ float g_wq[DIM * DIM];        // transposed [N][K], rna-rounded
__device__ float g_wk[DIM * DIM];
__device__ float g_wv[DIM * DIM];
__device__ float g_wo[DIM * DIM];

// ---------------------------------------------------------------------------
// Helpers
// ---------------------------------------------------------------------------
__device__ __forceinline__ uint32_t smem_u32(const void* p) {
    uint32_t a;
    asm("{ .reg .u64 t; cvta.to.shared.u64 t, %1; cvt.u32.u64 %0, t; }"
        : "=r"(a) : "l"(p));
    return a;
}

__device__ __forceinline__ void cp16(uint32_t smem, const void* g) {
    asm volatile("cp.async.cg.shared.global [%0], [%1], 16;" :: "r"(smem), "l"(g));
}
__device__ __forceinline__ void cp_commit() {
    asm volatile("cp.async.commit_group;" ::: "memory");
}
template <int N>
__device__ __forceinline__ void cp_wait() {
    asm volatile("cp.async.wait_group %0;" :: "n"(N) : "memory");
}

__device__ __forceinline__ uint32_t lds_u32(uint32_t addr) {
    uint32_t v;
    asm volatile("ld.shared.b32 %0, [%1];" : "=r"(v) : "r"(addr));
    return v;
}
__device__ __forceinline__ float rna_f32(float x) {
    uint32_t u;
    asm("cvt.rna.tf32.f32 %0, %1;" : "=r"(u) : "f"(x));
    return __uint_as_float(u);
}

__device__ __forceinline__ void mma_tf32(float* d, const uint32_t* a,
                                         uint32_t b0, uint32_t b1) {
    asm volatile(
        "mma.sync.aligned.m16n8k8.row.col.f32.tf32.tf32.f32 "
        "{%0,%1,%2,%3}, {%4,%5,%6,%7}, {%8,%9}, {%0,%1,%2,%3};"
        : "+f"(d[0]), "+f"(d[1]), "+f"(d[2]), "+f"(d[3])
        : "r"(a[0]), "r"(a[1]), "r"(a[2]), "r"(a[3]), "r"(b0), "r"(b1));
}

// ---------------------------------------------------------------------------
// RoPE tables
// ---------------------------------------------------------------------------
__global__ void rope_inv_kernel() {
    int j = threadIdx.x;
    if (j < HALF) {
        double inv = exp(-((double)(2 * j) / (double)DIM) * log(10000.0));
        g_invf[j] = (float)inv;
    }
}

__global__ void rope_tab_kernel() {
    int idx = blockIdx.x * 256 + threadIdx.x;
    int s = idx >> 9;
    int j = idx & (HALF - 1);
    float arg = (float)s * g_invf[j];
    float sn, cs;
    sincosf(arg, &sn, &cs);
    g_cos[idx] = cs;
    g_sin[idx] = sn;
}

// ---------------------------------------------------------------------------
// Activations: fp32 -> RNA(tf32)-rounded fp32, same layout (float4)
// ---------------------------------------------------------------------------
__global__ void act_round_kernel(const float* __restrict__ X,
                                 float* __restrict__ Y) {
    int i = (blockIdx.x * 256 + threadIdx.x) * 4;
    float4 x = *(const float4*)(X + i);
    x.x = rna_f32(x.x); x.y = rna_f32(x.y);
    x.z = rna_f32(x.z); x.w = rna_f32(x.w);
    *(float4*)(Y + i) = x;
}

// ---------------------------------------------------------------------------
// All 4 weight transposes in ONE launch. blockIdx.z selects the matrix.
// W [K][N] fp32 -> transposed [N][K] fp32, RNA-rounded to tf32 precision.
// ---------------------------------------------------------------------------
__global__ void convert_w4_kernel(const float* __restrict__ W0,
                                  const float* __restrict__ W1,
                                  const float* __restrict__ W2,
                                  const float* __restrict__ W3,
                                  float* __restrict__ T0, float* __restrict__ T1,
                                  float* __restrict__ T2, float* __restrict__ T3) {
    __shared__ float t[32][33];
    const float* W = (blockIdx.z == 0) ? W0 : (blockIdx.z == 1) ? W1
                   : (blockIdx.z == 2) ? W2 : W3;
    float* T = (blockIdx.z == 0) ? T0 : (blockIdx.z == 1) ? T1
             : (blockIdx.z == 2) ? T2 : T3;
    int k0 = blockIdx.y * 32, n0 = blockIdx.x * 32;
    int tx = threadIdx.x, ty = threadIdx.y;   // 32 x 8
#pragma unroll
    for (int i = 0; i < 32; i += 8)
        t[ty + i][tx] = W[(size_t)(k0 + ty + i) * DIM + n0 + tx];
    __syncthreads();
#pragma unroll
    for (int i = 0; i < 32; i += 8) {
        float x = t[tx][ty + i];              // W[k0+tx][n0+ty+i]
        T[(size_t)(n0 + ty + i) * DIM + k0 + tx] = rna_f32(x);
    }
}

// ---------------------------------------------------------------------------
// tf32 single-product GEMM:  C[M,N] = A @ B^T + bias  (A, B pre-RNA-rounded)
// CTA 128x256, 8 warps (2Mx4N), warp tile 64x64, K-chunk 32, 3 stages.
// Register double-buffering at ks granularity: fragments for ks+1 load while
// the 32 MMAs of ks issue -> LDS latency hides under tensor work.
// ---------------------------------------------------------------------------
__global__ void __launch_bounds__(256, 1)
gemm_tf32(const float* __restrict__ A, const float* __restrict__ B,
          const float* __restrict__ bias, float* __restrict__ C) {
    extern __shared__ __align__(1024) char smem[];
    const int tid  = threadIdx.x;
    const int wid  = tid >> 5;
    const int lane = tid & 31;
    const int row0 = blockIdx.y * GM;
    const int col0 = blockIdx.x * GN;
    const uint32_t sb = smem_u32(smem);

    const int wm = wid >> 2;            // 0..1
    const int wn = wid & 3;             // 0..3
    const int m_base = wm * 64;
    const int n_base = wn * 64;

    float acc[4][8][4];
#pragma unroll
    for (int i = 0; i < 4; i++)
#pragma unroll
        for (int j = 0; j < 8; j++)
#pragma unroll
            for (int e = 0; e < 4; e++) acc[i][j][e] = 0.0f;

    // --- chunk loader: A 128 rows x 8 segs, B 256 rows x 8 segs (16B each) ---
    auto issue = [&](int c) {
        const uint32_t st = sb + (uint32_t)(c % NSTAGE) * STAGE_BYTES;
        const int k0 = c * GKC;
#pragma unroll
        for (int i = 0; i < 4; i++) {
            int seg = tid + i * 256;
            int r  = seg >> 3;
            int s8 = seg & 7;
            cp16(st + RA + r * RSTRIDE + s8 * 16,
                 A + (size_t)(row0 + r) * DIM + k0 + s8 * 4);
        }
#pragma unroll
        for (int i = 0; i < 8; i++) {
            int seg = tid + i * 256;
            int r  = seg >> 3;
            int s8 = seg & 7;
            cp16(st + RB + r * RSTRIDE + s8 * 16,
                 B + (size_t)(col0 + r) * DIM + k0 + s8 * 4);
        }
        cp_commit();
    };

    issue(0); issue(1); issue(2);

    for (int c = 0; c < NCHUNK; c++) {
        cp_wait<2>();
        __syncthreads();
        const uint32_t st = sb + (uint32_t)(c % NSTAGE) * STAGE_BYTES;
        const uint32_t abase = st + RA + (m_base + (lane >> 2)) * RSTRIDE + (lane & 3) * 4;
        const uint32_t bbase = st + RB + (n_base + (lane >> 2)) * RSTRIDE + (lane & 3) * 4;

        uint32_t af[2][4][4], bf[2][8][2];

        auto load_frags = [&](int ks, int buf) {
            const int kb = ks * 32;
#pragma unroll
            for (int mi = 0; mi < 4; mi++) {
                uint32_t base = abase + mi * (16 * RSTRIDE) + kb;
                af[buf][mi][0] = lds_u32(base);
                af[buf][mi][1] = lds_u32(base + 8 * RSTRIDE);
                af[buf][mi][2] = lds_u32(base + 16);
                af[buf][mi][3] = lds_u32(base + 8 * RSTRIDE + 16);
            }
#pragma unroll
            for (int nj = 0; nj < 8; nj++) {
                uint32_t base = bbase + nj * (8 * RSTRIDE) + kb;
                bf[buf][nj][0] = lds_u32(base);
                bf[buf][nj][1] = lds_u32(base + 16);
            }
        };

        load_frags(0, 0);
#pragma unroll
        for (int ks = 0; ks < 4; ks++) {
            if (ks < 3) load_frags(ks + 1, (ks + 1) & 1);
            const int cb = ks & 1;
#pragma unroll
            for (int mi = 0; mi < 4; mi++)
#pragma unroll
                for (int nj = 0; nj < 8; nj++)
                    mma_tf32(acc[mi][nj], af[cb][mi], bf[cb][nj][0], bf[cb][nj][1]);
        }
        __syncthreads();
        if (c + NSTAGE < NCHUNK) issue(c + NSTAGE);
    }

    // Epilogue: add bias, store fp32
    const int rw = row0 + m_base;
    const int cw = col0 + n_base;
#pragma unroll
    for (int nj = 0; nj < 8; nj++) {
        int n = cw + nj * 8 + (lane & 3) * 2;
        float bx = __ldg(&bias[n]);
        float by = __ldg(&bias[n + 1]);
#pragma unroll
        for (int mi = 0; mi < 4; mi++) {
            int r = rw + mi * 16 + (lane >> 2);
            float2 v0 = make_float2(acc[mi][nj][0] + bx, acc[mi][nj][1] + by);
            float2 v1 = make_float2(acc[mi][nj][2] + bx, acc[mi][nj][3] + by);
            *(float2*)(C + (size_t)r * DIM + n)       = v0;
            *(float2*)(C + (size_t)(r + 8) * DIM + n) = v1;
        }
    }
}

// ---------------------------------------------------------------------------
// Per-token attention, vectorized:
//   float4 q/k/v loads, conflict-free padded qr/kr (stride 66),
//   fully parallel softmax via shfl(width 16), float4 ctx + scrambled store.
// Scramble: ctx[b,s,h,e] -> row h*128 + s/16, col (s%16)*64 + e
// ---------------------------------------------------------------------------
#define QKPAD 66

__global__ __launch_bounds__(256)
void attn_kernel(float* __restrict__ attn_out, int write_attn) {
    __shared__ float q[DIM], k[DIM], v[DIM];
    __shared__ float qr[HEADS * QKPAD], kr[HEADS * QKPAD];
    __shared__ float sc[256];

    int t   = blockIdx.x;
    int b   = t >> 11;
    int s   = t & (SEQ - 1);
    int tid = threadIdx.x;
    int d   = tid * 4;

    // Load q,k,v: one float4 per thread each (coalesced)
    ((float4*)q)[tid] = ((const float4*)(g_q + (size_t)t * DIM))[tid];
    ((float4*)k)[tid] = ((const float4*)(g_k + (size_t)t * DIM))[tid];
    ((float4*)v)[tid] = ((const float4*)(g_v + (size_t)t * DIM))[tid];
    __syncthreads();

    // RoPE: thread handles 4 consecutive d (same half, same head-row)
    {
        int j  = d & (HALF - 1);
        int pd = (d < HALF) ? d + HALF : d - HALF;
        float sgn = (d < HALF) ? -1.0f : 1.0f;
        float4 c4 = *(const float4*)(g_cos + (size_t)s * HALF + j);
        float4 s4 = *(const float4*)(g_sin + (size_t)s * HALF + j);
        float4 qv = *(float4*)(q + d),  qp = *(float4*)(q + pd);
        float4 kv = *(float4*)(k + d),  kp = *(float4*)(k + pd);
        int row = d >> 6, e = d & 63;
        float* qd = qr + row * QKPAD + e;
        float* kd = kr + row * QKPAD + e;
        qd[0] = qv.x * c4.x + sgn * qp.x * s4.x;
        qd[1] = qv.y * c4.y + sgn * qp.y * s4.y;
        qd[2] = qv.z * c4.z + sgn * qp.z * s4.z;
        qd[3] = qv.w * c4.w + sgn * qp.w * s4.w;
        kd[0] = kv.x * c4.x + sgn * kp.x * s4.x;
        kd[1] = kv.y * c4.y + sgn * kp.y * s4.y;
        kd[2] = kv.z * c4.z + sgn * kp.z * s4.z;
        kd[3] = kv.w * c4.w + sgn * kp.w * s4.w;
    }
    __syncthreads();

    // Scores + softmax, one thread per (i,j). kr stride 66 -> banks 2j+e,
    // conflict-free across the 16 lanes sharing i.
    {
        int i = tid >> 4, j = tid & 15;
        const float* qp = qr + i * QKPAD;
        const float* kp = kr + j * QKPAD;
        float sum = 0.0f;
#pragma unroll
        for (int e = 0; e < HD; e++) sum += qp[e] * kp[e];
        sum *= 0.125f;
        float m = sum;
#pragma unroll
        for (int off = 8; off > 0; off >>= 1)
            m = fmaxf(m, __shfl_xor_sync(0xFFFFFFFFu, m, off, 16));
        float ex = expf(sum - m);
        float tot = ex;
#pragma unroll
        for (int off = 8; off > 0; off >>= 1)
            tot += __shfl_xor_sync(0xFFFFFFFFu, tot, off, 16);
        float p = ex / tot;
        sc[tid] = p;
        if (write_attn) attn_out[(size_t)t * 256 + tid] = p;
    }
    __syncthreads();

    // ctx: thread computes out[i][e..e+3]; v float4 reads conflict-free.
    {
        int i = d >> 6, e = d & 63;
        float4 acc = make_float4(0.f, 0.f, 0.f, 0.f);
        const float* pr = sc + i * 16;
#pragma unroll
        for (int j = 0; j < HEADS; j++) {
            float p = pr[j];
            float4 vv = *(float4*)(v + j * HD + e);
            acc.x += p * vv.x; acc.y += p * vv.y;
            acc.z += p * vv.z; acc.w += p * vv.w;
        }
        int r = i * (SEQ / HEADS) + (s >> 4);
        int c = ((s & 15) << 6) | e;
        acc.x = rna_f32(acc.x); acc.y = rna_f32(acc.y);
        acc.z = rna_f32(acc.z); acc.w = rna_f32(acc.w);
        *(float4*)(g_xx + (size_t)b * SEQ * DIM + (size_t)r * DIM + c) = acc;
    }
}

// ---------------------------------------------------------------------------
// Host launcher. Launch #6 (skip-5 capture) is gemm_tf32 (Q projection).
// ---------------------------------------------------------------------------
extern "C" void kernel_launch(void* const* d_in, const int* in_sizes, int n_in,
                              void* d_out, int out_size) {
    const float* inputs  = (const float*)d_in[0];
    const float* context = (const float*)d_in[1];
    const float* Wq = (const float*)d_in[2];
    const float* bq = (const float*)d_in[3];
    const float* Wk = (const float*)d_in[4];
    const float* bk = (const float*)d_in[5];
    const float* Wv = (const float*)d_in[6];
    const float* bv = (const float*)d_in[7];
    const float* Wo = (const float*)d_in[8];
    const float* bo = (const float*)d_in[9];
    float* out = (float*)d_out;

    cudaFuncSetAttribute(gemm_tf32, cudaFuncAttributeMaxDynamicSharedMemorySize,
                         SMEM_TOTAL);

    float *pq, *pk, *pv, *pxx, *pxa, *pxc, *pwq, *pwk, *pwv, *pwo;
    cudaGetSymbolAddress((void**)&pq,  g_q);
    cudaGetSymbolAddress((void**)&pk,  g_k);
    cudaGetSymbolAddress((void**)&pv,  g_v);
    cudaGetSymbolAddress((void**)&pxx, g_xx);
    cudaGetSymbolAddress((void**)&pxa, g_xa);
    cudaGetSymbolAddress((void**)&pxc, g_xc);
    cudaGetSymbolAddress((void**)&pwq, g_wq);
    cudaGetSymbolAddress((void**)&pwk, g_wk);
    cudaGetSymbolAddress((void**)&pwv, g_wv);
    cudaGetSymbolAddress((void**)&pwo, g_wo);

    const int out_elems  = MTOK * DIM;
    const int attn_elems = MTOK * HEADS * HEADS;
    int write_attn = (out_size >= out_elems + attn_elems) ? 1 : 0;
    float* attn_out = out + out_elems;

    dim3 ggrid(DIM / GN, MTOK / GM);   // (4, 32) = 128 CTAs

    // #1: weight transposes (one launch)
    convert_w4_kernel<<<dim3(32, 32, 4), dim3(32, 8)>>>(Wq, Wk, Wv, Wo,
                                                        pwq, pwk, pwv, pwo);
    // #2-3: activation pre-rounding (RNA to tf32 grid)
    act_round_kernel<<<(MTOK * DIM) / 1024, 256>>>(inputs,  pxa);
    act_round_kernel<<<(MTOK * DIM) / 1024, 256>>>(context, pxc);
    // #4-5: RoPE tables
    rope_inv_kernel<<<1, 512>>>();
    rope_tab_kernel<<<(SEQ * HALF) / 256, 256>>>();
    // #6-8: Q/K/V projections  <-- ncu captures #6 (gemm Q)
    gemm_tf32<<<ggrid, 256, SMEM_TOTAL>>>(pxa, pwq, bq, pq);
    gemm_tf32<<<ggrid, 256, SMEM_TOTAL>>>(pxc, pwk, bk, pk);
    gemm_tf32<<<ggrid, 256, SMEM_TOTAL>>>(pxc, pwv, bv, pv);
    // #9: RoPE + per-token head attention + scramble
    attn_kernel<<<MTOK, 256>>>(attn_out, write_attn);
    // #10: O projection
    gemm_tf32<<<ggrid, 256, SMEM_TOTAL>>>(pxx, pwo, bo, out);
}

// round 10
// speedup vs baseline: 1.3585x; 1.0148x over previous
#include <cuda_runtime.h>
#include <stdint.h>
#include <math.h>

// Problem constants
#define BATCH 2
#define SEQ   2048
#define DIM   1024
#define HEADS 16
#define HD    64
#define MTOK  (BATCH * SEQ)            // 4096 tokens
#define HALF  (DIM / 2)                // 512

// tf32 GEMM tiling: CTA 128x256, 8 warps (2Mx4N), warp tile 64x64, K-chunk 32
#define GM 128
#define GN 256
#define GKC 32
#define NCHUNK (DIM / GKC)             // 32
#define NSTAGE 4
#define RSTRIDE 144                     // padded row stride bytes (36 floats)
#define RA 0
#define RB (128 * RSTRIDE)              // 18432
#define STAGE_BYTES ((128 + 256) * RSTRIDE) // 55296
#define SMEM_TOTAL (NSTAGE * STAGE_BYTES)   // 221184 (< 227KB limit)

// ---------------------------------------------------------------------------
// Device scratch (no cudaMalloc allowed)
// ---------------------------------------------------------------------------
__device__ float g_q[MTOK * DIM];
__device__ float g_k[MTOK * DIM];
__device__ float g_v[MTOK * DIM];
__device__ float g_xx[MTOK * DIM];       // scrambled ctx (rna-rounded)
__device__ float g_xa[MTOK * DIM];       // rna(inputs)
__device__ float g_xc[MTOK * DIM];       // rna(context)
__device__ float g_cos[SEQ * HALF];
__device__ float g_sin[SEQ * HALF];
__device__ float g_invf[HALF];

__device__ float g_wq[DIM * DIM];        // transposed [N][K], rna-rounded
__device__ float g_wk[DIM * DIM];
__device__ float g_wv[DIM * DIM];
__device__ float g_wo[DIM * DIM];

// ---------------------------------------------------------------------------
// Helpers
// ---------------------------------------------------------------------------
__device__ __forceinline__ uint32_t smem_u32(const void* p) {
    uint32_t a;
    asm("{ .reg .u64 t; cvta.to.shared.u64 t, %1; cvt.u32.u64 %0, t; }"
        : "=r"(a) : "l"(p));
    return a;
}

__device__ __forceinline__ void cp16(uint32_t smem, const void* g) {
    asm volatile("cp.async.cg.shared.global [%0], [%1], 16;" :: "r"(smem), "l"(g));
}
__device__ __forceinline__ void cp_commit() {
    asm volatile("cp.async.commit_group;" ::: "memory");
}
template <int N>
__device__ __forceinline__ void cp_wait() {
    asm volatile("cp.async.wait_group %0;" :: "n"(N) : "memory");
}

__device__ __forceinline__ uint32_t lds_u32(uint32_t addr) {
    uint32_t v;
    asm volatile("ld.shared.b32 %0, [%1];" : "=r"(v) : "r"(addr));
    return v;
}
__device__ __forceinline__ float rna_f32(float x) {
    uint32_t u;
    asm("cvt.rna.tf32.f32 %0, %1;" : "=r"(u) : "f"(x));
    return __uint_as_float(u);
}

__device__ __forceinline__ void mma_tf32(float* d, const uint32_t* a,
                                         uint32_t b0, uint32_t b1) {
    asm volatile(
        "mma.sync.aligned.m16n8k8.row.col.f32.tf32.tf32.f32 "
        "{%0,%1,%2,%3}, {%4,%5,%6,%7}, {%8,%9}, {%0,%1,%2,%3};"
        : "+f"(d[0]), "+f"(d[1]), "+f"(d[2]), "+f"(d[3])
        : "r"(a[0]), "r"(a[1]), "r"(a[2]), "r"(a[3]), "r"(b0), "r"(b1));
}

// ---------------------------------------------------------------------------
// RoPE tables
// ---------------------------------------------------------------------------
__global__ void rope_inv_kernel() {
    int j = threadIdx.x;
    if (j < HALF) {
        double inv = exp(-((double)(2 * j) / (double)DIM) * log(10000.0));
        g_invf[j] = (float)inv;
    }
}

__global__ void rope_tab_kernel() {
    int idx = blockIdx.x * 256 + threadIdx.x;
    int s = idx >> 9;
    int j = idx & (HALF - 1);
    float arg = (float)s * g_invf[j];
    float sn, cs;
    sincosf(arg, &sn, &cs);
    g_cos[idx] = cs;
    g_sin[idx] = sn;
}

// ---------------------------------------------------------------------------
// Activations: fp32 -> RNA(tf32)-rounded fp32, same layout (float4)
// ---------------------------------------------------------------------------
__global__ void act_round_kernel(const float* __restrict__ X,
                                 float* __restrict__ Y) {
    int i = (blockIdx.x * 256 + threadIdx.x) * 4;
    float4 x = *(const float4*)(X + i);
    x.x = rna_f32(x.x); x.y = rna_f32(x.y);
    x.z = rna_f32(x.z); x.w = rna_f32(x.w);
    *(float4*)(Y + i) = x;
}

// ---------------------------------------------------------------------------
// All 4 weight transposes in ONE launch. blockIdx.z selects the matrix.
// W [K][N] fp32 -> transposed [N][K] fp32, RNA-rounded to tf32 precision.
// ---------------------------------------------------------------------------
__global__ void convert_w4_kernel(const float* __restrict__ W0,
                                  const float* __restrict__ W1,
                                  const float* __restrict__ W2,
                                  const float* __restrict__ W3) {
    __shared__ float t[32][33];
    const float* W = (blockIdx.z == 0) ? W0 : (blockIdx.z == 1) ? W1
                   : (blockIdx.z == 2) ? W2 : W3;
    float* T = (blockIdx.z == 0) ? g_wq : (blockIdx.z == 1) ? g_wk
             : (blockIdx.z == 2) ? g_wv : g_wo;
    int k0 = blockIdx.y * 32, n0 = blockIdx.x * 32;
    int tx = threadIdx.x, ty = threadIdx.y;   // 32 x 8
#pragma unroll
    for (int i = 0; i < 32; i += 8)
        t[ty + i][tx] = W[(size_t)(k0 + ty + i) * DIM + n0 + tx];
    __syncthreads();
#pragma unroll
    for (int i = 0; i < 32; i += 8) {
        float x = t[tx][ty + i];              // W[k0+tx][n0+ty+i]
        T[(size_t)(n0 + ty + i) * DIM + k0 + tx] = rna_f32(x);
    }
}

// ---------------------------------------------------------------------------
// tf32 GEMM body:  C[M,N] = A @ B^T + bias  (A, B pre-RNA-rounded)
// CTA 128x256, 8 warps (2Mx4N), warp tile 64x64, K-chunk 32, 4 stages.
// SINGLE barrier per chunk: issue(c+3) targets stage (c-1)%4, whose readers
// all passed this iteration's top barrier. Register double-buffered frags.
// ---------------------------------------------------------------------------
__device__ __forceinline__ void gemm_body(
    const float* __restrict__ A, const float* __restrict__ B,
    const float* __restrict__ bias, float* __restrict__ C,
    char* smem, int row0, int col0) {
    const int tid  = threadIdx.x;
    const int wid  = tid >> 5;
    const int lane = tid & 31;
    const uint32_t sb = smem_u32(smem);

    const int wm = wid >> 2;            // 0..1
    const int wn = wid & 3;             // 0..3
    const int m_base = wm * 64;
    const int n_base = wn * 64;

    float acc[4][8][4];
#pragma unroll
    for (int i = 0; i < 4; i++)
#pragma unroll
        for (int j = 0; j < 8; j++)
#pragma unroll
            for (int e = 0; e < 4; e++) acc[i][j][e] = 0.0f;

    auto issue = [&](int c) {
        const uint32_t st = sb + (uint32_t)(c & (NSTAGE - 1)) * STAGE_BYTES;
        const int k0 = c * GKC;
#pragma unroll
        for (int i = 0; i < 4; i++) {
            int seg = tid + i * 256;
            int r  = seg >> 3;
            int s8 = seg & 7;
            cp16(st + RA + r * RSTRIDE + s8 * 16,
                 A + (size_t)(row0 + r) * DIM + k0 + s8 * 4);
        }
#pragma unroll
        for (int i = 0; i < 8; i++) {
            int seg = tid + i * 256;
            int r  = seg >> 3;
            int s8 = seg & 7;
            cp16(st + RB + r * RSTRIDE + s8 * 16,
                 B + (size_t)(col0 + r) * DIM + k0 + s8 * 4);
        }
        cp_commit();
    };

    issue(0); issue(1); issue(2);

    for (int c = 0; c < NCHUNK; c++) {
        cp_wait<2>();
        __syncthreads();
        // stage (c+3)%4 == (c-1)%4: all readers passed the barrier above.
        if (c + 3 < NCHUNK) issue(c + 3);

        const uint32_t st = sb + (uint32_t)(c & (NSTAGE - 1)) * STAGE_BYTES;
        const uint32_t abase = st + RA + (m_base + (lane >> 2)) * RSTRIDE + (lane & 3) * 4;
        const uint32_t bbase = st + RB + (n_base + (lane >> 2)) * RSTRIDE + (lane & 3) * 4;

        uint32_t af[2][4][4], bf[2][8][2];

        auto load_frags = [&](int ks, int buf) {
            const int kb = ks * 32;
#pragma unroll
            for (int mi = 0; mi < 4; mi++) {
                uint32_t base = abase + mi * (16 * RSTRIDE) + kb;
                af[buf][mi][0] = lds_u32(base);
                af[buf][mi][1] = lds_u32(base + 8 * RSTRIDE);
                af[buf][mi][2] = lds_u32(base + 16);
                af[buf][mi][3] = lds_u32(base + 8 * RSTRIDE + 16);
            }
#pragma unroll
            for (int nj = 0; nj < 8; nj++) {
                uint32_t base = bbase + nj * (8 * RSTRIDE) + kb;
                bf[buf][nj][0] = lds_u32(base);
                bf[buf][nj][1] = lds_u32(base + 16);
            }
        };

        load_frags(0, 0);
#pragma unroll
        for (int ks = 0; ks < 4; ks++) {
            if (ks < 3) load_frags(ks + 1, (ks + 1) & 1);
            const int cb = ks & 1;
#pragma unroll
            for (int mi = 0; mi < 4; mi++)
#pragma unroll
                for (int nj = 0; nj < 8; nj++)
                    mma_tf32(acc[mi][nj], af[cb][mi], bf[cb][nj][0], bf[cb][nj][1]);
        }
    }

    // Epilogue: add bias, store fp32
    const int rw = row0 + m_base;
    const int cw = col0 + n_base;
#pragma unroll
    for (int nj = 0; nj < 8; nj++) {
        int n = cw + nj * 8 + (lane & 3) * 2;
        float bx = __ldg(&bias[n]);
        float by = __ldg(&bias[n + 1]);
#pragma unroll
        for (int mi = 0; mi < 4; mi++) {
            int r = rw + mi * 16 + (lane >> 2);
            float2 v0 = make_float2(acc[mi][nj][0] + bx, acc[mi][nj][1] + by);
            float2 v1 = make_float2(acc[mi][nj][2] + bx, acc[mi][nj][3] + by);
            *(float2*)(C + (size_t)r * DIM + n)       = v0;
            *(float2*)(C + (size_t)(r + 8) * DIM + n) = v1;
        }
    }
}

// Fused Q/K/V projections: blockIdx.z selects {A, W, bias, C}.
__global__ void __launch_bounds__(256, 1)
gemm_qkv(const float* __restrict__ bq, const float* __restrict__ bk,
         const float* __restrict__ bv) {
    extern __shared__ __align__(1024) char smem[];
    int z = blockIdx.z;
    const float* A    = (z == 0) ? g_xa : g_xc;
    const float* B    = (z == 0) ? g_wq : (z == 1) ? g_wk : g_wv;
    const float* bias = (z == 0) ? bq   : (z == 1) ? bk   : bv;
    float* C          = (z == 0) ? g_q  : (z == 1) ? g_k  : g_v;
    gemm_body(A, B, bias, C, smem, blockIdx.y * GM, blockIdx.x * GN);
}

// Generic single GEMM (used for the O projection).
__global__ void __launch_bounds__(256, 1)
gemm_tf32(const float* __restrict__ A, const float* __restrict__ B,
          const float* __restrict__ bias, float* __restrict__ C) {
    extern __shared__ __align__(1024) char smem[];
    gemm_body(A, B, bias, C, smem, blockIdx.y * GM, blockIdx.x * GN);
}

// ---------------------------------------------------------------------------
// Per-token attention, vectorized (see round 9): float4 I/O, padded qr/kr,
// shfl softmax, scrambled rna-rounded ctx store.
// ---------------------------------------------------------------------------
#define QKPAD 66

__global__ __launch_bounds__(256)
void attn_kernel(float* __restrict__ attn_out, int write_attn) {
    __shared__ float q[DIM], k[DIM], v[DIM];
    __shared__ float qr[HEADS * QKPAD], kr[HEADS * QKPAD];
    __shared__ float sc[256];

    int t   = blockIdx.x;
    int b   = t >> 11;
    int s   = t & (SEQ - 1);
    int tid = threadIdx.x;
    int d   = tid * 4;

    ((float4*)q)[tid] = ((const float4*)(g_q + (size_t)t * DIM))[tid];
    ((float4*)k)[tid] = ((const float4*)(g_k + (size_t)t * DIM))[tid];
    ((float4*)v)[tid] = ((const float4*)(g_v + (size_t)t * DIM))[tid];
    __syncthreads();

    {
        int j  = d & (HALF - 1);
        int pd = (d < HALF) ? d + HALF : d - HALF;
        float sgn = (d < HALF) ? -1.0f : 1.0f;
        float4 c4 = *(const float4*)(g_cos + (size_t)s * HALF + j);
        float4 s4 = *(const float4*)(g_sin + (size_t)s * HALF + j);
        float4 qv = *(float4*)(q + d),  qp = *(float4*)(q + pd);
        float4 kv = *(float4*)(k + d),  kp = *(float4*)(k + pd);
        int row = d >> 6, e = d & 63;
        float* qd = qr + row * QKPAD + e;
        float* kd = kr + row * QKPAD + e;
        qd[0] = qv.x * c4.x + sgn * qp.x * s4.x;
        qd[1] = qv.y * c4.y + sgn * qp.y * s4.y;
        qd[2] = qv.z * c4.z + sgn * qp.z * s4.z;
        qd[3] = qv.w * c4.w + sgn * qp.w * s4.w;
        kd[0] = kv.x * c4.x + sgn * kp.x * s4.x;
        kd[1] = kv.y * c4.y + sgn * kp.y * s4.y;
        kd[2] = kv.z * c4.z + sgn * kp.z * s4.z;
        kd[3] = kv.w * c4.w + sgn * kp.w * s4.w;
    }
    __syncthreads();

    {
        int i = tid >> 4, j = tid & 15;
        const float* qp = qr + i * QKPAD;
        const float* kp = kr + j * QKPAD;
        float sum = 0.0f;
#pragma unroll
        for (int e = 0; e < HD; e++) sum += qp[e] * kp[e];
        sum *= 0.125f;
        float m = sum;
#pragma unroll
        for (int off = 8; off > 0; off >>= 1)
            m = fmaxf(m, __shfl_xor_sync(0xFFFFFFFFu, m, off, 16));
        float ex = expf(sum - m);
        float tot = ex;
#pragma unroll
        for (int off = 8; off > 0; off >>= 1)
            tot += __shfl_xor_sync(0xFFFFFFFFu, tot, off, 16);
        float p = ex / tot;
        sc[tid] = p;
        if (write_attn) attn_out[(size_t)t * 256 + tid] = p;
    }
    __syncthreads();

    {
        int i = d >> 6, e = d & 63;
        float4 acc = make_float4(0.f, 0.f, 0.f, 0.f);
        const float* pr = sc + i * 16;
#pragma unroll
        for (int j = 0; j < HEADS; j++) {
            float p = pr[j];
            float4 vv = *(float4*)(v + j * HD + e);
            acc.x += p * vv.x; acc.y += p * vv.y;
            acc.z += p * vv.z; acc.w += p * vv.w;
        }
        int r = i * (SEQ / HEADS) + (s >> 4);
        int c = ((s & 15) << 6) | e;
        acc.x = rna_f32(acc.x); acc.y = rna_f32(acc.y);
        acc.z = rna_f32(acc.z); acc.w = rna_f32(acc.w);
        *(float4*)(g_xx + (size_t)b * SEQ * DIM + (size_t)r * DIM + c) = acc;
    }
}

// ---------------------------------------------------------------------------
// Host launcher. Launch #4 == fused QKV GEMM  <-- ncu capture slot.
// ---------------------------------------------------------------------------
extern "C" void kernel_launch(void* const* d_in, const int* in_sizes, int n_in,
                              void* d_out, int out_size) {
    const float* inputs  = (const float*)d_in[0];
    const float* context = (const float*)d_in[1];
    const float* Wq = (const float*)d_in[2];
    const float* bq = (const float*)d_in[3];
    const float* Wk = (const float*)d_in[4];
    const float* bk = (const float*)d_in[5];
    const float* Wv = (const float*)d_in[6];
    const float* bv = (const float*)d_in[7];
    const float* Wo = (const float*)d_in[8];
    const float* bo = (const float*)d_in[9];
    float* out = (float*)d_out;

    cudaFuncSetAttribute(gemm_qkv, cudaFuncAttributeMaxDynamicSharedMemorySize,
                         SMEM_TOTAL);
    cudaFuncSetAttribute(gemm_tf32, cudaFuncAttributeMaxDynamicSharedMemorySize,
                         SMEM_TOTAL);

    float *pxx, *pxa, *pxc, *pwo;
    cudaGetSymbolAddress((void**)&pxx, g_xx);
    cudaGetSymbolAddress((void**)&pxa, g_xa);
    cudaGetSymbolAddress((void**)&pxc, g_xc);
    cudaGetSymbolAddress((void**)&pwo, g_wo);

    const int out_elems  = MTOK * DIM;
    const int attn_elems = MTOK * HEADS * HEADS;
    int write_attn = (out_size >= out_elems + attn_elems) ? 1 : 0;
    float* attn_out = out + out_elems;

    // #1: weight transposes (one launch)
    convert_w4_kernel<<<dim3(32, 32, 4), dim3(32, 8)>>>(Wq, Wk, Wv, Wo);
    // #2-3: activation pre-rounding
    act_round_kernel<<<(MTOK * DIM) / 1024, 256>>>(inputs,  pxa);
    act_round_kernel<<<(MTOK * DIM) / 1024, 256>>>(context, pxc);
    // #4: fused Q/K/V projections  <-- ncu capture slot
    gemm_qkv<<<dim3(DIM / GN, MTOK / GM, 3), 256, SMEM_TOTAL>>>(bq, bk, bv);
    // #5-6: RoPE tables
    rope_inv_kernel<<<1, 512>>>();
    rope_tab_kernel<<<(SEQ * HALF) / 256, 256>>>();
    // #7: RoPE + per-token head attention + scramble
    attn_kernel<<<MTOK, 256>>>(attn_out, write_attn);
    // #8: O projection
    gemm_tf32<<<dim3(DIM / GN, MTOK / GM), 256, SMEM_TOTAL>>>(pxx, pwo, bo, out);
}